// round 14
// baseline (speedup 1.0000x reference)
#include <cuda_runtime.h>
#include <cuda_bf16.h>
#include <cstdint>

// Problem constants (fixed by the reference)
#define NQ      256      // number of queries (D)
#define KDIM    256      // descriptor dim (C)
#define KHALF   128      // GEMM partial-K (screen); rest bounded by Cauchy-Schwarz
#define DBP     257      // places_db row pitch in floats (256 dims + id)
#define NT      64       // db rows per tile
#define THREADS 512
#define MAXH    1024
#define MIN_SIM_F 0.8f
#define SCAN_BASE 0.77f  // 0.8 minus margin for bf16 GEMM error (tail norms exact)
#define TOPK    10
#define GRID_SMS 152

#define APITCH  136      // bf16 row pitch for K=128 (272B rows: LDSM conflict-free)
#define BPITCH  136
#define A_BYTES (NQ * APITCH * 2)        // 69632
#define B_BYTES (NT * BPITCH * 2)        // 17408
#define B0_OFF  A_BYTES
#define B1_OFF  (B0_OFF + B_BYTES)
#define QN_OFF  (B1_OFF + B_BYTES)       // ||q2|| per query [NQ]
#define NRM_OFF (QN_OFF + NQ * 4)        // 3 x [NT] tail-norm^2 buffers
#define SMEM_TOTAL (NRM_OFF + 3 * NT * 4)

// Scratch (device globals — zero-initialized at load; finalize re-zeros each call)
__device__ int g_hitCnt[NQ];
__device__ int g_hitIdx[NQ * MAXH];
__device__ int g_done;

__device__ __forceinline__ uint32_t smem_u32(const void* p) {
    uint32_t a;
    asm("{ .reg .u64 t; cvta.to.shared.u64 t, %1; cvt.u32.u64 %0, t; }" : "=r"(a) : "l"(p));
    return a;
}

#define LDSM4(r0, r1, r2, r3, addr) \
    asm volatile("ldmatrix.sync.aligned.m8n8.x4.shared.b16 {%0,%1,%2,%3}, [%4];" \
        : "=r"(r0), "=r"(r1), "=r"(r2), "=r"(r3) : "r"(addr))

__device__ __forceinline__ void mma_bf16(float* acc, uint32_t a0, uint32_t a1,
                                         uint32_t a2, uint32_t a3,
                                         uint32_t b0, uint32_t b1) {
    asm volatile(
        "mma.sync.aligned.m16n8k16.row.col.f32.bf16.bf16.f32 "
        "{%0,%1,%2,%3}, {%4,%5,%6,%7}, {%8,%9}, {%0,%1,%2,%3};\n"
        : "+f"(acc[0]), "+f"(acc[1]), "+f"(acc[2]), "+f"(acc[3])
        : "r"(a0), "r"(a1), "r"(a2), "r"(a3), "r"(b0), "r"(b1));
}

// ---------------------------------------------------------------------------
// Fused: bf16 GEMM over K=128 + per-pair Cauchy-Schwarz screen (tail norms
// computed for free from staged f32 registers during convert) + last-CTA
// exact finalize. One __syncthreads per tile; Bs double-buffered; norm
// buffers triple-rotated so zeroing needs no extra barrier.
// ---------------------------------------------------------------------------
__global__ void __launch_bounds__(THREADS, 1)
fused_kernel(const float* __restrict__ boxes,
             const float* __restrict__ desc,
             const float* __restrict__ db,
             float* __restrict__ out,
             int ndb, int ntiles)
{
    extern __shared__ __align__(16) unsigned char smem[];
    __nv_bfloat16* As   = reinterpret_cast<__nv_bfloat16*>(smem);       // [NQ][APITCH]
    __nv_bfloat16* Bs0  = reinterpret_cast<__nv_bfloat16*>(smem + B0_OFF);
    __nv_bfloat16* Bs1  = reinterpret_cast<__nv_bfloat16*>(smem + B1_OFF);
    float*         qn2S = reinterpret_cast<float*>(smem + QN_OFF);      // [NQ]
    float*         nrmS = reinterpret_cast<float*>(smem + NRM_OFF);     // [3][NT]

    const int tid  = threadIdx.x;
    const int lane = tid & 31;
    const int warp = tid >> 5;   // 0..15
    const int wm   = warp >> 1;  // 0..7  : M rows [wm*32, wm*32+32)
    const int wn   = warp & 1;   // 0..1  : N cols [wn*32, wn*32+32)

    const int NF4 = (NT * DBP) / 4;   // 4112
    const int G   = gridDim.x;

    // ---- Convert A (descriptors, f32 -> bf16 smem), only k < 128 ----
    {
        const float4* A4 = reinterpret_cast<const float4*>(desc);
        #pragma unroll 4
        for (int i = tid; i < (NQ * KDIM) / 4; i += THREADS) {
            float4 v = A4[i];
            int e = i * 4;
            int r = e >> 8;
            int c = e & 255;
            if (c < KHALF) {
                __nv_bfloat162* p = reinterpret_cast<__nv_bfloat162*>(As + r * APITCH + c);
                p[0] = __floats2bfloat162_rn(v.x, v.y);
                p[1] = __floats2bfloat162_rn(v.z, v.w);
            }
        }
    }

    // ---- One-time: qn2S[m] = ||q2_m|| exactly from fp32 desc (cols 128..255) ----
    {
        int qr = tid >> 1, qs = tid & 1;   // 2 threads per query row
        const float4* rp =
            reinterpret_cast<const float4*>(desc + qr * KDIM + KHALF + qs * 64);
        float s = 0.f;
        #pragma unroll
        for (int j = 0; j < 16; j++) {
            float4 f = rp[j];
            s = fmaf(f.x, f.x, s); s = fmaf(f.y, f.y, s);
            s = fmaf(f.z, f.z, s); s = fmaf(f.w, f.w, s);
        }
        s += __shfl_xor_sync(0xffffffffu, s, 1);
        if (qs == 0) qn2S[qr] = sqrtf(s);
    }
    // zero all three norm buffers
    for (int z = tid; z < 3 * NT; z += THREADS) nrmS[z] = 0.f;
    __syncthreads();

    // per-thread ||q2|| for its 4 accumulator m-rows
    float q2r[2][2];
    float q2mx = 0.f;
    #pragma unroll
    for (int mi = 0; mi < 2; mi++)
        #pragma unroll
        for (int ph = 0; ph < 2; ph++) {
            q2r[mi][ph] = qn2S[wm * 32 + mi * 16 + ph * 8 + (lane >> 2)];
            q2mx = fmaxf(q2mx, q2r[mi][ph]);
        }

    // ---- Per-lane ldmatrix base addresses ----
    const uint32_t smem_base = smem_u32(smem);
    const uint32_t Bs_base   = smem_base + B0_OFF;
    const int g  = lane >> 3;
    const int lr = lane & 7;
    uint32_t a_addr[2];
    #pragma unroll
    for (int mi = 0; mi < 2; mi++)
        a_addr[mi] = smem_base +
            (uint32_t)(((wm * 32 + mi * 16 + (g & 1) * 8 + lr) * APITCH + (g >> 1) * 8) * 2);
    uint32_t b_addr[2];
    #pragma unroll
    for (int h = 0; h < 2; h++)
        b_addr[h] = Bs_base +
            (uint32_t)(((wn * 32 + h * 16 + (g >> 1) * 8 + lr) * BPITCH + (g & 1) * 8) * 2);

    // ---- helpers as lambdas ----
    float4 st[9];
    auto stage = [&](int tt) {
        const float4* B4 = reinterpret_cast<const float4*>(db + (size_t)tt * (NT * DBP));
        int nf4 = (min(NT, ndb - tt * NT) * DBP) >> 2;
        #pragma unroll
        for (int it = 0; it < 9; it++) {
            int i = tid + it * THREADS;
            st[it] = (i < nf4) ? B4[i] : make_float4(0.f, 0.f, 0.f, 0.f);
        }
    };
    // convert + accumulate tail-square norms (cols 128..255) into nrm[]
    auto convert = [&](__nv_bfloat16* Bs, float* nrm) {
        #pragma unroll
        for (int it = 0; it < 9; it++) {
            int i = tid + it * THREADS;
            if (i < NF4) {
                int e = i * 4;
                int r = e / DBP;
                int c = e - r * DBP;
                float v[4] = { st[it].x, st[it].y, st[it].z, st[it].w };
                float ps = 0.f;
                #pragma unroll
                for (int j = 0; j < 4; j++) {
                    if (c < KHALF) {
                        Bs[r * BPITCH + c] = __float2bfloat16(v[j]);
                    } else if (c < KDIM) {
                        ps = fmaf(v[j], v[j], ps);   // tail squares (exclude id col)
                    }
                    if (++c == DBP) {
                        if (ps != 0.f) { atomicAdd(&nrm[r], ps); ps = 0.f; }
                        c = 0; r++;
                    }
                }
                if (ps != 0.f) atomicAdd(&nrm[r], ps);
            }
        }
    };

    // ---- Prologue: convert tile t0 into Bs0 + nrm[0], stage tile t1 ----
    int t = blockIdx.x;
    if (t < ntiles) {
        stage(t);
        convert(Bs0, nrmS);
        if (t + G < ntiles) stage(t + G);
    }
    __syncthreads();

    // ---- Main loop: ONE barrier per tile ----
    int k = 0;
    for (; t < ntiles; t += G, k++) {
        const int p = k & 1;
        const uint32_t bsel = p ? (uint32_t)B_BYTES : 0u;
        const int nq0 = k % 3;                  // epilogue reads this norm buffer
        const int nq1 = (k + 1) % 3;            // convert writes this one
        const int nq2 = (k + 2) % 3;            // zero this one (free this iter)

        // 1) MMA-issue(t) on Bs[p]
        float acc[2][4][4];
        #pragma unroll
        for (int mi = 0; mi < 2; mi++)
            #pragma unroll
            for (int ni = 0; ni < 4; ni++)
                #pragma unroll
                for (int cc = 0; cc < 4; cc++) acc[mi][ni][cc] = 0.f;

        #pragma unroll
        for (int ks = 0; ks < 8; ks++) {
            const uint32_t koff = (uint32_t)(ks * 32) + bsel;   // 16 bf16 = 32 bytes
            uint32_t a[2][4], bb[2][4];
            LDSM4(a[0][0], a[0][1], a[0][2], a[0][3], a_addr[0] + (uint32_t)(ks * 32));
            LDSM4(a[1][0], a[1][1], a[1][2], a[1][3], a_addr[1] + (uint32_t)(ks * 32));
            LDSM4(bb[0][0], bb[0][1], bb[0][2], bb[0][3], b_addr[0] + koff);
            LDSM4(bb[1][0], bb[1][1], bb[1][2], bb[1][3], b_addr[1] + koff);
            #pragma unroll
            for (int mi = 0; mi < 2; mi++) {
                mma_bf16(acc[mi][0], a[mi][0], a[mi][1], a[mi][2], a[mi][3], bb[0][0], bb[0][1]);
                mma_bf16(acc[mi][1], a[mi][0], a[mi][1], a[mi][2], a[mi][3], bb[0][2], bb[0][3]);
                mma_bf16(acc[mi][2], a[mi][0], a[mi][1], a[mi][2], a[mi][3], bb[1][0], bb[1][1]);
                mma_bf16(acc[mi][3], a[mi][0], a[mi][1], a[mi][2], a[mi][3], bb[1][2], bb[1][3]);
            }
        }

        // 2) zero next-next norm buffer (read finished last iteration; barrier-ordered)
        for (int z = tid; z < NT; z += THREADS) nrmS[nq2 * NT + z] = 0.f;

        // 3) convert(t+1) into Bs[~p] + nrm[nq1]  (overlaps tensor drain)
        if (t + G < ntiles) convert(p ? Bs0 : Bs1, nrmS + nq1 * NT);

        // 4) stage(t+2) — LDGs in flight across the next tile
        if (t + 2 * G < ntiles) stage(t + 2 * G);

        // 5) Epilogue: per-pair screen using exact tail norms from nrm[nq0]
        {
            const float* nb = nrmS + nq0 * NT + wn * 32;
            const int row0 = t * NT;
            #pragma unroll
            for (int ni = 0; ni < 4; ni++) {
                #pragma unroll
                for (int pp = 0; pp < 2; pp++) {
                    int nl = ni * 8 + ((lane & 3) << 1) + pp;     // 0..31 within warp range
                    float x2n = sqrtf(nb[nl]);
                    float mx = fmaxf(fmaxf(acc[0][ni][pp], acc[0][ni][pp + 2]),
                                     fmaxf(acc[1][ni][pp], acc[1][ni][pp + 2]));
                    if (fmaf(q2mx, x2n, mx) >= SCAN_BASE) {
                        int n = row0 + wn * 32 + nl;
                        if (n < ndb) {
                            #pragma unroll
                            for (int mi = 0; mi < 2; mi++)
                                #pragma unroll
                                for (int ph = 0; ph < 2; ph++) {
                                    if (fmaf(q2r[mi][ph], x2n, acc[mi][ni][pp + 2 * ph])
                                        >= SCAN_BASE) {
                                        int m = wm * 32 + mi * 16 + ph * 8 + (lane >> 2);
                                        int pos = atomicAdd(&g_hitCnt[m], 1);
                                        if (pos < MAXH) g_hitIdx[m * MAXH + pos] = n;
                                    }
                                }
                        }
                    }
                }
            }
        }

        __syncthreads();   // generation barrier
    }

    // =======================================================================
    // Completion ticket: last CTA runs the exact finalize.
    // =======================================================================
    __threadfence();
    __syncthreads();
    __shared__ int s_tk;
    if (tid == 0) s_tk = atomicAdd(&g_done, 1);
    __syncthreads();
    if (s_tk != (int)gridDim.x - 1) return;
    __threadfence();

    // reuse dynamic smem for box data
    float* fx1 = reinterpret_cast<float*>(smem);
    float* fy1 = fx1 + NQ;
    float* fx2 = fy1 + NQ;
    float* fy2 = fx2 + NQ;
    float* far_ = fy2 + NQ;
    int*   flb = reinterpret_cast<int*>(far_ + NQ);

    float ts[TOPK];
    int   tn[TOPK], ids[TOPK];
    int K = 0, label = -1;
    float x1 = 0.f, y1 = 0.f, x2 = 0.f, y2 = 0.f, area = 0.f;

    if (tid < NQ) {
        const int d = tid;
        int cnt = __ldcg(&g_hitCnt[d]);
        if (cnt > MAXH) cnt = MAXH;
        for (int i = 0; i < cnt; i++) {
            int n = __ldcg(&g_hitIdx[d * MAXH + i]);
            float s = 0.f;
            const float* qa = desc + (size_t)d * KDIM;
            const float* xb = db + (size_t)n * DBP;
            for (int kk = 0; kk < KDIM; kk++) s = fmaf(qa[kk], xb[kk], s);
            if (s < MIN_SIM_F) continue;
            int p = K;
            while (p > 0 && (s > ts[p - 1] || (s == ts[p - 1] && n < tn[p - 1]))) p--;
            if (p < TOPK) {
                int end = (K < TOPK) ? K : (TOPK - 1);
                for (int q = end; q > p; q--) { ts[q] = ts[q - 1]; tn[q] = tn[q - 1]; }
                ts[p] = s; tn[p] = n;
                if (K < TOPK) K++;
            }
        }
        for (int kk = 0; kk < K; kk++)
            ids[kk] = (int)db[(size_t)tn[kk] * DBP + (DBP - 1)];
        int best_cnt = 0, best_id = 0x7fffffff;
        for (int kk = 0; kk < K; kk++) {
            int c = 0;
            for (int j = 0; j < K; j++) c += (ids[j] == ids[kk]);
            if (c > best_cnt || (c == best_cnt && ids[kk] < best_id)) {
                best_cnt = c; best_id = ids[kk];
            }
        }
        label = (best_cnt > 0) ? best_id : -1;

        x1 = boxes[d * 4 + 0]; y1 = boxes[d * 4 + 1];
        x2 = boxes[d * 4 + 2]; y2 = boxes[d * 4 + 3];
        area = (x2 - x1) * (y2 - y1);
        fx1[d] = x1; fy1[d] = y1; fx2[d] = x2; fy2[d] = y2;
        far_[d] = area; flb[d] = label;

        g_hitCnt[d] = 0;       // reset for next replay
    }
    if (tid == 0) g_done = 0;  // reset ticket
    __syncthreads();

    if (tid < NQ) {
        const int d = tid;
        bool removed = false;
        if (label >= 0) {
            for (int j = 0; j < NQ; j++) {
                if (j == d || flb[j] != label) continue;
                float ix1 = fmaxf(x1, fx1[j]);
                float iy1 = fmaxf(y1, fy1[j]);
                float ix2 = fminf(x2, fx2[j]);
                float iy2 = fminf(y2, fy2[j]);
                float inter = fmaxf(ix2 - ix1, 0.f) * fmaxf(iy2 - iy1, 0.f);
                float asmall = fminf(area, far_[j]);
                float ov = (asmall > 0.f) ? (inter / asmall) : 0.f;
                if (ov >= 0.8f && far_[j] <= area) removed = true;
            }
        }
        int result = removed ? -1 : label;

        float score = 0.f;
        for (int kk = 0; kk < K; kk++)
            if (ids[kk] == result) score = fmaxf(score, ts[kk]);

        for (int i = d; i < NQ * 4; i += NQ) out[i] = boxes[i];
        out[NQ * 4 + d] = score;
        out[NQ * 5 + d] = (float)result;
    }
}

// ---------------------------------------------------------------------------
extern "C" void kernel_launch(void* const* d_in, const int* in_sizes, int n_in,
                              void* d_out, int out_size)
{
    const float* boxes = (const float*)d_in[0];
    const float* desc  = (const float*)d_in[1];
    const float* db    = (const float*)d_in[2];
    int db_elems = in_sizes[2];
    for (int i = 0; i < n_in; i++) {
        if (in_sizes[i] == NQ * 4)         boxes = (const float*)d_in[i];
        else if (in_sizes[i] == NQ * KDIM) desc  = (const float*)d_in[i];
        else                               { db = (const float*)d_in[i]; db_elems = in_sizes[i]; }
    }
    int ndb    = db_elems / DBP;
    int ntiles = (ndb + NT - 1) / NT;

    cudaFuncSetAttribute(fused_kernel,
                         cudaFuncAttributeMaxDynamicSharedMemorySize, SMEM_TOTAL);

    fused_kernel<<<GRID_SMS, THREADS, SMEM_TOTAL>>>(boxes, desc, db,
                                                    (float*)d_out, ndb, ntiles);
    (void)out_size;
}

// round 15
// speedup vs baseline: 2.4033x; 2.4033x over previous
#include <cuda_runtime.h>
#include <cuda_bf16.h>
#include <cstdint>

// Problem constants (fixed by the reference)
#define NQ      256      // number of queries (D)
#define KDIM    256      // descriptor dim (C)
#define DBP     257      // places_db row pitch in floats (256 dims + id)
#define NT      64       // db rows per tile
#define THREADS 512
#define MAXH    1024
#define MIN_SIM_F 0.8f
#define SCAN_THR  0.78f  // bf16 scan threshold (validated in R6: error << 0.02)
#define TOPK    10
#define GRID_SMS 152

#define APITCH  264      // bf16 row pitch for K=256 (528B rows: LDSM conflict-free)
#define BPITCH  264
#define A_BYTES (NQ * APITCH * 2)        // 135168
#define B_BYTES (NT * BPITCH * 2)        // 33792
#define B0_OFF  A_BYTES
#define B1_OFF  (B0_OFF + B_BYTES)
#define SMEM_TOTAL (B1_OFF + B_BYTES)    // 202752

// Scratch (device globals — zero-initialized at load; finalize re-zeros each call)
__device__ int g_hitCnt[NQ];
__device__ int g_hitIdx[NQ * MAXH];
__device__ int g_done;

__device__ __forceinline__ uint32_t smem_u32(const void* p) {
    uint32_t a;
    asm("{ .reg .u64 t; cvta.to.shared.u64 t, %1; cvt.u32.u64 %0, t; }" : "=r"(a) : "l"(p));
    return a;
}

#define LDSM4(r0, r1, r2, r3, addr) \
    asm volatile("ldmatrix.sync.aligned.m8n8.x4.shared.b16 {%0,%1,%2,%3}, [%4];" \
        : "=r"(r0), "=r"(r1), "=r"(r2), "=r"(r3) : "r"(addr))

__device__ __forceinline__ void mma_bf16(float* acc, uint32_t a0, uint32_t a1,
                                         uint32_t a2, uint32_t a3,
                                         uint32_t b0, uint32_t b1) {
    asm volatile(
        "mma.sync.aligned.m16n8k16.row.col.f32.bf16.bf16.f32 "
        "{%0,%1,%2,%3}, {%4,%5,%6,%7}, {%8,%9}, {%0,%1,%2,%3};\n"
        : "+f"(acc[0]), "+f"(acc[1]), "+f"(acc[2]), "+f"(acc[3])
        : "r"(a0), "r"(a1), "r"(a2), "r"(a3), "r"(b0), "r"(b1));
}

// ---------------------------------------------------------------------------
// Fused: full-K bf16 GEMM + constant-threshold scan + last-CTA exact finalize.
// ONE __syncthreads per tile; Bs double-buffered; convert/stage overlap the
// tensor-pipe drain of the current tile's MMAs.
// ---------------------------------------------------------------------------
__global__ void __launch_bounds__(THREADS, 1)
fused_kernel(const float* __restrict__ boxes,
             const float* __restrict__ desc,
             const float* __restrict__ db,
             float* __restrict__ out,
             int ndb, int ntiles)
{
    extern __shared__ __align__(16) unsigned char smem[];
    __nv_bfloat16* As  = reinterpret_cast<__nv_bfloat16*>(smem);       // [NQ][APITCH]
    __nv_bfloat16* Bs0 = reinterpret_cast<__nv_bfloat16*>(smem + B0_OFF);
    __nv_bfloat16* Bs1 = reinterpret_cast<__nv_bfloat16*>(smem + B1_OFF);

    const int tid  = threadIdx.x;
    const int lane = tid & 31;
    const int warp = tid >> 5;   // 0..15
    const int wm   = warp >> 1;  // 0..7  : M rows [wm*32, wm*32+32)
    const int wn   = warp & 1;   // 0..1  : N cols [wn*32, wn*32+32)

    const int NF4 = (NT * DBP) / 4;   // 4112
    const int G   = gridDim.x;

    // ---- Convert A (descriptors, f32 -> bf16 smem), full K ----
    {
        const float4* A4 = reinterpret_cast<const float4*>(desc);
        #pragma unroll 4
        for (int i = tid; i < (NQ * KDIM) / 4; i += THREADS) {
            float4 v = A4[i];
            int e = i * 4;
            int r = e >> 8;
            int c = e & 255;
            __nv_bfloat162* p = reinterpret_cast<__nv_bfloat162*>(As + r * APITCH + c);
            p[0] = __floats2bfloat162_rn(v.x, v.y);
            p[1] = __floats2bfloat162_rn(v.z, v.w);
        }
    }

    // ---- Per-lane ldmatrix base addresses ----
    const uint32_t smem_base = smem_u32(smem);
    const uint32_t Bs_base   = smem_base + B0_OFF;
    const int g  = lane >> 3;
    const int lr = lane & 7;
    uint32_t a_addr[2];
    #pragma unroll
    for (int mi = 0; mi < 2; mi++)
        a_addr[mi] = smem_base +
            (uint32_t)(((wm * 32 + mi * 16 + (g & 1) * 8 + lr) * APITCH + (g >> 1) * 8) * 2);
    uint32_t b_addr[2];
    #pragma unroll
    for (int h = 0; h < 2; h++)
        b_addr[h] = Bs_base +
            (uint32_t)(((wn * 32 + h * 16 + (g >> 1) * 8 + lr) * BPITCH + (g & 1) * 8) * 2);

    // ---- helpers ----
    float4 st[9];
    auto stage = [&](int tt) {
        const float4* B4 = reinterpret_cast<const float4*>(db + (size_t)tt * (NT * DBP));
        int nf4 = (min(NT, ndb - tt * NT) * DBP) >> 2;
        #pragma unroll
        for (int it = 0; it < 9; it++) {
            int i = tid + it * THREADS;
            st[it] = (i < nf4) ? B4[i] : make_float4(0.f, 0.f, 0.f, 0.f);
        }
    };
    auto convert = [&](__nv_bfloat16* Bs) {
        #pragma unroll
        for (int it = 0; it < 9; it++) {
            int i = tid + it * THREADS;
            if (i < NF4) {
                int e = i * 4;
                int r = e / DBP;
                int c = e - r * DBP;
                float v[4] = { st[it].x, st[it].y, st[it].z, st[it].w };
                #pragma unroll
                for (int j = 0; j < 4; j++) {
                    if (c < KDIM) Bs[r * BPITCH + c] = __float2bfloat16(v[j]);
                    if (++c == DBP) { c = 0; r++; }
                }
            }
        }
    };

    // ---- Prologue: stage+convert tile t0 into Bs0, stage tile t1 ----
    int t = blockIdx.x;
    if (t < ntiles) {
        stage(t);
        convert(Bs0);
        if (t + G < ntiles) stage(t + G);
    }
    __syncthreads();

    // ---- Main loop: ONE barrier per tile ----
    int k = 0;
    for (; t < ntiles; t += G, k++) {
        const int p = k & 1;
        const uint32_t bsel = p ? (uint32_t)B_BYTES : 0u;

        // 1) MMA-issue(t) on Bs[p]: warp tile 32(M) x 32(N), K=256
        float acc[2][4][4];
        #pragma unroll
        for (int mi = 0; mi < 2; mi++)
            #pragma unroll
            for (int ni = 0; ni < 4; ni++)
                #pragma unroll
                for (int cc = 0; cc < 4; cc++) acc[mi][ni][cc] = 0.f;

        #pragma unroll
        for (int ks = 0; ks < 16; ks++) {
            const uint32_t akoff = (uint32_t)(ks * 32);          // 16 bf16 = 32 bytes
            const uint32_t bkoff = akoff + bsel;
            uint32_t a[2][4], bb[2][4];
            LDSM4(a[0][0], a[0][1], a[0][2], a[0][3], a_addr[0] + akoff);
            LDSM4(a[1][0], a[1][1], a[1][2], a[1][3], a_addr[1] + akoff);
            LDSM4(bb[0][0], bb[0][1], bb[0][2], bb[0][3], b_addr[0] + bkoff);
            LDSM4(bb[1][0], bb[1][1], bb[1][2], bb[1][3], b_addr[1] + bkoff);
            #pragma unroll
            for (int mi = 0; mi < 2; mi++) {
                mma_bf16(acc[mi][0], a[mi][0], a[mi][1], a[mi][2], a[mi][3], bb[0][0], bb[0][1]);
                mma_bf16(acc[mi][1], a[mi][0], a[mi][1], a[mi][2], a[mi][3], bb[0][2], bb[0][3]);
                mma_bf16(acc[mi][2], a[mi][0], a[mi][1], a[mi][2], a[mi][3], bb[1][0], bb[1][1]);
                mma_bf16(acc[mi][3], a[mi][0], a[mi][1], a[mi][2], a[mi][3], bb[1][2], bb[1][3]);
            }
        }

        // 2) convert(t+1) into Bs[~p]  (overlaps tensor drain)
        if (t + G < ntiles) convert(p ? Bs0 : Bs1);

        // 3) stage(t+2) — LDGs in flight across the next tile
        if (t + 2 * G < ntiles) stage(t + 2 * G);

        // 4) Epilogue: max-tree vs constant threshold; rare append
        float vmax = -1e30f;
        #pragma unroll
        for (int mi = 0; mi < 2; mi++)
            #pragma unroll
            for (int ni = 0; ni < 4; ni++)
                #pragma unroll
                for (int cc = 0; cc < 4; cc++) vmax = fmaxf(vmax, acc[mi][ni][cc]);

        if (vmax >= SCAN_THR) {
            const int row0 = t * NT;
            #pragma unroll
            for (int mi = 0; mi < 2; mi++)
                #pragma unroll
                for (int ni = 0; ni < 4; ni++)
                    #pragma unroll
                    for (int cc = 0; cc < 4; cc++) {
                        if (acc[mi][ni][cc] >= SCAN_THR) {
                            int m = wm * 32 + mi * 16 + (lane >> 2) + ((cc >> 1) << 3);
                            int n = row0 + wn * 32 + ni * 8 + ((lane & 3) << 1) + (cc & 1);
                            if (n < ndb) {
                                int pos = atomicAdd(&g_hitCnt[m], 1);
                                if (pos < MAXH) g_hitIdx[m * MAXH + pos] = n;
                            }
                        }
                    }
        }

        __syncthreads();   // generation barrier (Bs[p] free, Bs[~p] published)
    }

    // =======================================================================
    // Completion ticket: last CTA runs the exact finalize.
    // =======================================================================
    __threadfence();
    __syncthreads();
    __shared__ int s_tk;
    if (tid == 0) s_tk = atomicAdd(&g_done, 1);
    __syncthreads();
    if (s_tk != (int)gridDim.x - 1) return;
    __threadfence();

    // reuse dynamic smem for box data
    float* fx1 = reinterpret_cast<float*>(smem);
    float* fy1 = fx1 + NQ;
    float* fx2 = fy1 + NQ;
    float* fy2 = fx2 + NQ;
    float* far_ = fy2 + NQ;
    int*   flb = reinterpret_cast<int*>(far_ + NQ);

    float ts[TOPK];
    int   tn[TOPK], ids[TOPK];
    int K = 0, label = -1;
    float x1 = 0.f, y1 = 0.f, x2 = 0.f, y2 = 0.f, area = 0.f;

    if (tid < NQ) {
        const int d = tid;
        int cnt = __ldcg(&g_hitCnt[d]);
        if (cnt > MAXH) cnt = MAXH;
        for (int i = 0; i < cnt; i++) {
            int n = __ldcg(&g_hitIdx[d * MAXH + i]);
            float s = 0.f;
            const float* qa = desc + (size_t)d * KDIM;
            const float* xb = db + (size_t)n * DBP;
            for (int kk = 0; kk < KDIM; kk++) s = fmaf(qa[kk], xb[kk], s);
            if (s < MIN_SIM_F) continue;
            int p = K;
            while (p > 0 && (s > ts[p - 1] || (s == ts[p - 1] && n < tn[p - 1]))) p--;
            if (p < TOPK) {
                int end = (K < TOPK) ? K : (TOPK - 1);
                for (int q = end; q > p; q--) { ts[q] = ts[q - 1]; tn[q] = tn[q - 1]; }
                ts[p] = s; tn[p] = n;
                if (K < TOPK) K++;
            }
        }
        for (int kk = 0; kk < K; kk++)
            ids[kk] = (int)db[(size_t)tn[kk] * DBP + (DBP - 1)];
        int best_cnt = 0, best_id = 0x7fffffff;
        for (int kk = 0; kk < K; kk++) {
            int c = 0;
            for (int j = 0; j < K; j++) c += (ids[j] == ids[kk]);
            if (c > best_cnt || (c == best_cnt && ids[kk] < best_id)) {
                best_cnt = c; best_id = ids[kk];
            }
        }
        label = (best_cnt > 0) ? best_id : -1;

        x1 = boxes[d * 4 + 0]; y1 = boxes[d * 4 + 1];
        x2 = boxes[d * 4 + 2]; y2 = boxes[d * 4 + 3];
        area = (x2 - x1) * (y2 - y1);
        fx1[d] = x1; fy1[d] = y1; fx2[d] = x2; fy2[d] = y2;
        far_[d] = area; flb[d] = label;

        g_hitCnt[d] = 0;       // reset for next replay
    }
    if (tid == 0) g_done = 0;  // reset ticket
    __syncthreads();

    if (tid < NQ) {
        const int d = tid;
        bool removed = false;
        if (label >= 0) {
            for (int j = 0; j < NQ; j++) {
                if (j == d || flb[j] != label) continue;
                float ix1 = fmaxf(x1, fx1[j]);
                float iy1 = fmaxf(y1, fy1[j]);
                float ix2 = fminf(x2, fx2[j]);
                float iy2 = fminf(y2, fy2[j]);
                float inter = fmaxf(ix2 - ix1, 0.f) * fmaxf(iy2 - iy1, 0.f);
                float asmall = fminf(area, far_[j]);
                float ov = (asmall > 0.f) ? (inter / asmall) : 0.f;
                if (ov >= 0.8f && far_[j] <= area) removed = true;
            }
        }
        int result = removed ? -1 : label;

        float score = 0.f;
        for (int kk = 0; kk < K; kk++)
            if (ids[kk] == result) score = fmaxf(score, ts[kk]);

        for (int i = d; i < NQ * 4; i += NQ) out[i] = boxes[i];
        out[NQ * 4 + d] = score;
        out[NQ * 5 + d] = (float)result;
    }
}

// ---------------------------------------------------------------------------
extern "C" void kernel_launch(void* const* d_in, const int* in_sizes, int n_in,
                              void* d_out, int out_size)
{
    const float* boxes = (const float*)d_in[0];
    const float* desc  = (const float*)d_in[1];
    const float* db    = (const float*)d_in[2];
    int db_elems = in_sizes[2];
    for (int i = 0; i < n_in; i++) {
        if (in_sizes[i] == NQ * 4)         boxes = (const float*)d_in[i];
        else if (in_sizes[i] == NQ * KDIM) desc  = (const float*)d_in[i];
        else                               { db = (const float*)d_in[i]; db_elems = in_sizes[i]; }
    }
    int ndb    = db_elems / DBP;
    int ntiles = (ndb + NT - 1) / NT;

    cudaFuncSetAttribute(fused_kernel,
                         cudaFuncAttributeMaxDynamicSharedMemorySize, SMEM_TOTAL);

    fused_kernel<<<GRID_SMS, THREADS, SMEM_TOTAL>>>(boxes, desc, db,
                                                    (float*)d_out, ndb, ntiles);
    (void)out_size;
}

// round 17
// speedup vs baseline: 5.0409x; 2.0975x over previous
#include <cuda_runtime.h>
#include <cuda_bf16.h>
#include <cstdint>

// Problem constants (fixed by the reference)
#define NQ      256      // number of queries (D)
#define KDIM    256      // descriptor dim (C)
#define KHALF   128      // GEMM partial-K (screen); tail bounded by Cauchy-Schwarz
#define DBP     257      // places_db row pitch in floats (256 dims + id)
#define NT      64       // db rows per tile
#define THREADS 512
#define MAXH    1024
#define MIN_SIM_F 0.8f
#define SCAN_BASE 0.77f  // 0.8 minus margin (bf16 GEMM err <= 0.002, slack 0.028)
#define TOPK    10
#define GRID_SMS 152

#define APITCH  136      // bf16 row pitch for K=128 (272B rows: LDSM conflict-free)
#define BPITCH  136
#define A_BYTES (NQ * APITCH * 2)        // 69632
#define B_BYTES (NT * BPITCH * 2)        // 17408
#define B0_OFF  A_BYTES
#define B1_OFF  (B0_OFF + B_BYTES)
#define QN_OFF  (B1_OFF + B_BYTES)       // ||q2||^2 per query [NQ]
#define NRM_OFF (QN_OFF + NQ * 4)        // [2][NT] ||x1||^2 buffers
#define SMEM_TOTAL (NRM_OFF + 2 * NT * 4)

// Scratch (device globals — zero-initialized at load; finalize re-zeros each call)
__device__ int g_hitCnt[NQ];
__device__ int g_hitIdx[NQ * MAXH];
__device__ int g_done;

__device__ __forceinline__ uint32_t smem_u32(const void* p) {
    uint32_t a;
    asm("{ .reg .u64 t; cvta.to.shared.u64 t, %1; cvt.u32.u64 %0, t; }" : "=r"(a) : "l"(p));
    return a;
}

#define LDSM4(r0, r1, r2, r3, addr) \
    asm volatile("ldmatrix.sync.aligned.m8n8.x4.shared.b16 {%0,%1,%2,%3}, [%4];" \
        : "=r"(r0), "=r"(r1), "=r"(r2), "=r"(r3) : "r"(addr))

__device__ __forceinline__ void mma_bf16(float* acc, uint32_t a0, uint32_t a1,
                                         uint32_t a2, uint32_t a3,
                                         uint32_t b0, uint32_t b1) {
    asm volatile(
        "mma.sync.aligned.m16n8k16.row.col.f32.bf16.bf16.f32 "
        "{%0,%1,%2,%3}, {%4,%5,%6,%7}, {%8,%9}, {%0,%1,%2,%3};\n"
        : "+f"(acc[0]), "+f"(acc[1]), "+f"(acc[2]), "+f"(acc[3])
        : "r"(a0), "r"(a1), "r"(a2), "r"(a3), "r"(b0), "r"(b1));
}

// ---------------------------------------------------------------------------
// Fused: bf16 GEMM over K=128, halved DRAM stream (tail cols never read),
// free row norms via warp reduction, sqrt-free per-pair C-S screen,
// last-CTA exact finalize. ONE __syncthreads per tile.
// ---------------------------------------------------------------------------
__global__ void __launch_bounds__(THREADS, 1)
fused_kernel(const float* __restrict__ boxes,
             const float* __restrict__ desc,
             const float* __restrict__ db,
             float* __restrict__ out,
             int ndb, int ntiles)
{
    extern __shared__ __align__(16) unsigned char smem[];
    __nv_bfloat16* As   = reinterpret_cast<__nv_bfloat16*>(smem);       // [NQ][APITCH]
    __nv_bfloat16* Bs0  = reinterpret_cast<__nv_bfloat16*>(smem + B0_OFF);
    __nv_bfloat16* Bs1  = reinterpret_cast<__nv_bfloat16*>(smem + B1_OFF);
    float*         qn2S = reinterpret_cast<float*>(smem + QN_OFF);      // [NQ] ||q2||^2
    float*         nrmS = reinterpret_cast<float*>(smem + NRM_OFF);     // [2][NT] ||x1||^2

    const int tid  = threadIdx.x;
    const int lane = tid & 31;
    const int warp = tid >> 5;   // 0..15
    const int wm   = warp >> 1;  // 0..7  : M rows [wm*32, wm*32+32)
    const int wn   = warp & 1;   // 0..1  : N cols [wn*32, wn*32+32)
    const int G    = gridDim.x;

    // ---- Convert A (descriptors, f32 -> bf16 smem), only k < 128 ----
    {
        const float4* A4 = reinterpret_cast<const float4*>(desc);
        #pragma unroll 4
        for (int i = tid; i < (NQ * KDIM) / 4; i += THREADS) {
            float4 v = A4[i];
            int e = i * 4;
            int r = e >> 8;
            int c = e & 255;
            if (c < KHALF) {
                __nv_bfloat162* p = reinterpret_cast<__nv_bfloat162*>(As + r * APITCH + c);
                p[0] = __floats2bfloat162_rn(v.x, v.y);
                p[1] = __floats2bfloat162_rn(v.z, v.w);
            }
        }
    }

    // ---- One-time: qn2S[m] = ||q2_m||^2 exactly from fp32 desc (cols 128..255) ----
    {
        int qr = tid >> 1, qs = tid & 1;   // 2 threads per query row
        const float4* rp =
            reinterpret_cast<const float4*>(desc + qr * KDIM + KHALF + qs * 64);
        float s = 0.f;
        #pragma unroll
        for (int j = 0; j < 16; j++) {
            float4 f = rp[j];
            s = fmaf(f.x, f.x, s); s = fmaf(f.y, f.y, s);
            s = fmaf(f.z, f.z, s); s = fmaf(f.w, f.w, s);
        }
        s += __shfl_xor_sync(0xffffffffu, s, 1);
        if (qs == 0) qn2S[qr] = s;
    }
    __syncthreads();

    // per-thread ||q2||^2 for its 4 accumulator m-rows
    float q2sq[2][2];
    float q2mxsq = 0.f;
    #pragma unroll
    for (int mi = 0; mi < 2; mi++)
        #pragma unroll
        for (int ph = 0; ph < 2; ph++) {
            q2sq[mi][ph] = qn2S[wm * 32 + mi * 16 + ph * 8 + (lane >> 2)];
            q2mxsq = fmaxf(q2mxsq, q2sq[mi][ph]);
        }

    // ---- Per-lane ldmatrix base addresses ----
    const uint32_t smem_base = smem_u32(smem);
    const uint32_t Bs_base   = smem_base + B0_OFF;
    const int g  = lane >> 3;
    const int lr = lane & 7;
    uint32_t a_addr[2];
    #pragma unroll
    for (int mi = 0; mi < 2; mi++)
        a_addr[mi] = smem_base +
            (uint32_t)(((wm * 32 + mi * 16 + (g & 1) * 8 + lr) * APITCH + (g >> 1) * 8) * 2);
    uint32_t b_addr[2];
    #pragma unroll
    for (int h = 0; h < 2; h++)
        b_addr[h] = Bs_base +
            (uint32_t)(((wn * 32 + h * 16 + (g >> 1) * 8 + lr) * BPITCH + (g & 1) * 8) * 2);

    // ---- helpers ----
    // Row-aligned staging: warp w owns rows 4w..4w+3; for each row, 4 fully
    // coalesced 128B warp-LDGs (cols 0..127 only — tail never read).
    float v[16];
    auto stage = [&](int tt) {
        #pragma unroll
        for (int r = 0; r < 4; r++) {
            int nrow = tt * NT + warp * 4 + r;
            const float* rp = db + (size_t)nrow * DBP + lane;
            bool ok = (nrow < ndb);
            #pragma unroll
            for (int ch = 0; ch < 4; ch++)
                v[r * 4 + ch] = ok ? rp[ch * 32] : 0.f;
        }
    };
    // Convert staged regs -> Bs[pb] (bf16) + per-row ||x1||^2 via warp reduce.
    auto convert = [&](int pb) {
        __nv_bfloat16* Bs = pb ? Bs1 : Bs0;
        float* nb = nrmS + pb * NT;
        #pragma unroll
        for (int r = 0; r < 4; r++) {
            float s = 0.f;
            #pragma unroll
            for (int ch = 0; ch < 4; ch++) {
                float x = v[r * 4 + ch];
                Bs[(warp * 4 + r) * BPITCH + ch * 32 + lane] = __float2bfloat16(x);
                s = fmaf(x, x, s);
            }
            #pragma unroll
            for (int o = 16; o; o >>= 1) s += __shfl_xor_sync(0xffffffffu, s, o);
            if (lane == 0) nb[warp * 4 + r] = s;
        }
    };

    // ---- Prologue: stage+convert tile t0 into buf0, stage tile t1 ----
    int t = blockIdx.x;
    if (t < ntiles) {
        stage(t);
        convert(0);
        if (t + G < ntiles) stage(t + G);
    }
    __syncthreads();

    // ---- Main loop: ONE barrier per tile ----
    int k = 0;
    for (; t < ntiles; t += G, k++) {
        const int p = k & 1;
        const uint32_t bsel = p ? (uint32_t)B_BYTES : 0u;

        // 1) MMA(t) on Bs[p]: warp tile 32(M) x 32(N), K=128
        float acc[2][4][4];
        #pragma unroll
        for (int mi = 0; mi < 2; mi++)
            #pragma unroll
            for (int ni = 0; ni < 4; ni++)
                #pragma unroll
                for (int cc = 0; cc < 4; cc++) acc[mi][ni][cc] = 0.f;

        #pragma unroll
        for (int ks = 0; ks < 8; ks++) {
            const uint32_t akoff = (uint32_t)(ks * 32);   // 16 bf16 = 32 bytes
            const uint32_t bkoff = akoff + bsel;
            uint32_t a[2][4], bb[2][4];
            LDSM4(a[0][0], a[0][1], a[0][2], a[0][3], a_addr[0] + akoff);
            LDSM4(a[1][0], a[1][1], a[1][2], a[1][3], a_addr[1] + akoff);
            LDSM4(bb[0][0], bb[0][1], bb[0][2], bb[0][3], b_addr[0] + bkoff);
            LDSM4(bb[1][0], bb[1][1], bb[1][2], bb[1][3], b_addr[1] + bkoff);
            #pragma unroll
            for (int mi = 0; mi < 2; mi++) {
                mma_bf16(acc[mi][0], a[mi][0], a[mi][1], a[mi][2], a[mi][3], bb[0][0], bb[0][1]);
                mma_bf16(acc[mi][1], a[mi][0], a[mi][1], a[mi][2], a[mi][3], bb[0][2], bb[0][3]);
                mma_bf16(acc[mi][2], a[mi][0], a[mi][1], a[mi][2], a[mi][3], bb[1][0], bb[1][1]);
                mma_bf16(acc[mi][3], a[mi][0], a[mi][1], a[mi][2], a[mi][3], bb[1][2], bb[1][3]);
            }
        }

        // 2) Epilogue(t): sqrt-free per-pair screen  (acc dies here)
        //    hit iff acc >= 0.77  OR  (0.77-acc)^2 <= ||q2||^2 * (1-||x1||^2)
        {
            const float* nb = nrmS + p * NT + wn * 32;
            const int row0 = t * NT;
            #pragma unroll
            for (int ni = 0; ni < 4; ni++) {
                #pragma unroll
                for (int pp = 0; pp < 2; pp++) {
                    int nl = ni * 8 + ((lane & 3) << 1) + pp;
                    float x2sq = fmaxf(1.f - nb[nl], 0.f);
                    float mx = fmaxf(fmaxf(acc[0][ni][pp], acc[0][ni][pp + 2]),
                                     fmaxf(acc[1][ni][pp], acc[1][ni][pp + 2]));
                    float d = SCAN_BASE - mx;
                    if (d <= 0.f || d * d <= q2mxsq * x2sq) {
                        int n = row0 + wn * 32 + nl;
                        if (n < ndb) {
                            #pragma unroll
                            for (int mi = 0; mi < 2; mi++)
                                #pragma unroll
                                for (int ph = 0; ph < 2; ph++) {
                                    float dd = SCAN_BASE - acc[mi][ni][pp + 2 * ph];
                                    if (dd <= 0.f || dd * dd <= q2sq[mi][ph] * x2sq) {
                                        int m = wm * 32 + mi * 16 + ph * 8 + (lane >> 2);
                                        int pos = atomicAdd(&g_hitCnt[m], 1);
                                        if (pos < MAXH) g_hitIdx[m * MAXH + pos] = n;
                                    }
                                }
                        }
                    }
                }
            }
        }

        // 3) convert(t+1) into Bs[~p] + nrm[~p]
        if (t + G < ntiles) convert(p ^ 1);

        // 4) stage(t+2) — LDGs in flight across the next tile
        if (t + 2 * G < ntiles) stage(t + 2 * G);

        __syncthreads();   // generation barrier
    }

    // =======================================================================
    // Completion ticket: last CTA runs the exact finalize.
    // =======================================================================
    __threadfence();
    __syncthreads();
    __shared__ int s_tk;
    if (tid == 0) s_tk = atomicAdd(&g_done, 1);
    __syncthreads();
    if (s_tk != (int)gridDim.x - 1) return;
    __threadfence();

    // reuse dynamic smem for box data
    float* fx1 = reinterpret_cast<float*>(smem);
    float* fy1 = fx1 + NQ;
    float* fx2 = fy1 + NQ;
    float* fy2 = fx2 + NQ;
    float* far_ = fy2 + NQ;
    int*   flb = reinterpret_cast<int*>(far_ + NQ);

    float ts[TOPK];
    int   tn[TOPK], ids[TOPK];
    int K = 0, label = -1;
    float x1 = 0.f, y1 = 0.f, x2 = 0.f, y2 = 0.f, area = 0.f;

    if (tid < NQ) {
        const int d = tid;
        int cnt = __ldcg(&g_hitCnt[d]);
        if (cnt > MAXH) cnt = MAXH;
        for (int i = 0; i < cnt; i++) {
            int n = __ldcg(&g_hitIdx[d * MAXH + i]);
            float s = 0.f;
            const float* qa = desc + (size_t)d * KDIM;
            const float* xb = db + (size_t)n * DBP;
            for (int kk = 0; kk < KDIM; kk++) s = fmaf(qa[kk], xb[kk], s);
            if (s < MIN_SIM_F) continue;
            int p = K;
            while (p > 0 && (s > ts[p - 1] || (s == ts[p - 1] && n < tn[p - 1]))) p--;
            if (p < TOPK) {
                int end = (K < TOPK) ? K : (TOPK - 1);
                for (int q = end; q > p; q--) { ts[q] = ts[q - 1]; tn[q] = tn[q - 1]; }
                ts[p] = s; tn[p] = n;
                if (K < TOPK) K++;
            }
        }
        for (int kk = 0; kk < K; kk++)
            ids[kk] = (int)db[(size_t)tn[kk] * DBP + (DBP - 1)];
        int best_cnt = 0, best_id = 0x7fffffff;
        for (int kk = 0; kk < K; kk++) {
            int c = 0;
            for (int j = 0; j < K; j++) c += (ids[j] == ids[kk]);
            if (c > best_cnt || (c == best_cnt && ids[kk] < best_id)) {
                best_cnt = c; best_id = ids[kk];
            }
        }
        label = (best_cnt > 0) ? best_id : -1;

        x1 = boxes[d * 4 + 0]; y1 = boxes[d * 4 + 1];
        x2 = boxes[d * 4 + 2]; y2 = boxes[d * 4 + 3];
        area = (x2 - x1) * (y2 - y1);
        fx1[d] = x1; fy1[d] = y1; fx2[d] = x2; fy2[d] = y2;
        far_[d] = area; flb[d] = label;

        g_hitCnt[d] = 0;       // reset for next replay
    }
    if (tid == 0) g_done = 0;  // reset ticket
    __syncthreads();

    if (tid < NQ) {
        const int d = tid;
        bool removed = false;
        if (label >= 0) {
            for (int j = 0; j < NQ; j++) {
                if (j == d || flb[j] != label) continue;
                float ix1 = fmaxf(x1, fx1[j]);
                float iy1 = fmaxf(y1, fy1[j]);
                float ix2 = fminf(x2, fx2[j]);
                float iy2 = fminf(y2, fy2[j]);
                float inter = fmaxf(ix2 - ix1, 0.f) * fmaxf(iy2 - iy1, 0.f);
                float asmall = fminf(area, far_[j]);
                float ov = (asmall > 0.f) ? (inter / asmall) : 0.f;
                if (ov >= 0.8f && far_[j] <= area) removed = true;
            }
        }
        int result = removed ? -1 : label;

        float score = 0.f;
        for (int kk = 0; kk < K; kk++)
            if (ids[kk] == result) score = fmaxf(score, ts[kk]);

        for (int i = d; i < NQ * 4; i += NQ) out[i] = boxes[i];
        out[NQ * 4 + d] = score;
        out[NQ * 5 + d] = (float)result;
    }
}

// ---------------------------------------------------------------------------
extern "C" void kernel_launch(void* const* d_in, const int* in_sizes, int n_in,
                              void* d_out, int out_size)
{
    const float* boxes = (const float*)d_in[0];
    const float* desc  = (const float*)d_in[1];
    const float* db    = (const float*)d_in[2];
    int db_elems = in_sizes[2];
    for (int i = 0; i < n_in; i++) {
        if (in_sizes[i] == NQ * 4)         boxes = (const float*)d_in[i];
        else if (in_sizes[i] == NQ * KDIM) desc  = (const float*)d_in[i];
        else                               { db = (const float*)d_in[i]; db_elems = in_sizes[i]; }
    }
    int ndb    = db_elems / DBP;
    int ntiles = (ndb + NT - 1) / NT;

    cudaFuncSetAttribute(fused_kernel,
                         cudaFuncAttributeMaxDynamicSharedMemorySize, SMEM_TOTAL);

    fused_kernel<<<GRID_SMS, THREADS, SMEM_TOTAL>>>(boxes, desc, db,
                                                    (float*)d_out, ndb, ntiles);
    (void)out_size;
}